// round 15
// baseline (speedup 1.0000x reference)
#include <cuda_runtime.h>
#include <cuda_bf16.h>
#include <mma.h>
#include <math.h>
#include <stdint.h>

using namespace nvcuda;

#define BATCH 4
#define NPIX  4096
#define CH    512
#define DQ    64
#define MTOT  (BATCH*NPIX)

// Scratch (device globals: the sanctioned no-alloc workaround)
static __device__ __nv_bfloat16  g_xh[(size_t)MTOT * CH];           // bf16 x (16 MB)
static __device__ __nv_bfloat16  g_whh[CH * CH];                    // bf16 Wh
static __device__ __nv_bfloat16  g_wfg[CH * 2 * DQ];                // bf16 [Wf|Wg] 512x128
static __device__ __nv_bfloat16  g_fgh[MTOT * 2 * DQ];              // bf16 [f|g] (4 MB)
static __device__ __nv_bfloat16  g_vh[(size_t)MTOT * CH];           // 16 MB
static __device__ __nv_bfloat16  g_sh[(size_t)BATCH * NPIX * NPIX]; // 128 MB exp(S)
static __device__ float          g_rsum[MTOT];                      // row sums

// ---------------------------------------------------------------------------
// cp.async helpers
// ---------------------------------------------------------------------------
__device__ __forceinline__ void cp_async16(void* smem_dst, const void* gmem_src) {
    uint32_t sa = (uint32_t)__cvta_generic_to_shared(smem_dst);
    asm volatile("cp.async.cg.shared.global [%0], [%1], 16;\n" :: "r"(sa), "l"(gmem_src));
}
__device__ __forceinline__ void cp_commit() {
    asm volatile("cp.async.commit_group;\n");
}
__device__ __forceinline__ void cp_wait_all() {
    asm volatile("cp.async.wait_group 0;\n");
}
__device__ __forceinline__ void cp_wait_1() {
    asm volatile("cp.async.wait_group 1;\n");
}

__device__ __forceinline__ uint32_t pack_bf162(float lo, float hi) {
    __nv_bfloat162 h = __floats2bfloat162_rn(lo, hi);
    return *reinterpret_cast<uint32_t*>(&h);
}

// ---------------------------------------------------------------------------
// small prep kernels
// ---------------------------------------------------------------------------
__global__ void zero_rsum()
{
    g_rsum[blockIdx.x * 1024 + threadIdx.x] = 0.0f;
}

// float -> bf16, 4 elems per thread
__global__ void cvt_f32_bf16(const float* __restrict__ src, __nv_bfloat16* __restrict__ dst)
{
    const size_t i = (size_t)blockIdx.x * 256 + threadIdx.x;
    float4 v = reinterpret_cast<const float4*>(src)[i];
    uint2 o;
    o.x = pack_bf162(v.x, v.y);
    o.y = pack_bf162(v.z, v.w);
    reinterpret_cast<uint2*>(dst)[i] = o;
}

// build Wfg[512][128] = [Wf | Wg] in bf16
__global__ void build_wfg(const float* __restrict__ wf, const float* __restrict__ wg)
{
    const int i = blockIdx.x * 256 + threadIdx.x;   // 0 .. 512*64-1
    const int r = i >> 6, c = i & 63;
    g_wfg[r * 128 + c]      = __float2bfloat16(wf[r * 64 + c]);
    g_wfg[r * 128 + 64 + c] = __float2bfloat16(wg[r * 64 + c]);
}

// ---------------------------------------------------------------------------
// Narrow bf16 GEMM (for the N=128 fg projection): block 128x128, 8 warps,
// warp tile 64x32, K-tile 64, cp.async double-buffered.
// ---------------------------------------------------------------------------
#define GB_ALD 72
#define GB_BLD 136
#define GB_ABUF (128 * GB_ALD)     // 9216 bf16
#define GB_BBUF (64 * GB_BLD)      // 8704 bf16
#define GB_SMEM ((2 * GB_ABUF + 2 * GB_BBUF) * 2 + 8 * 272 * 4)

#define GB_LOAD_STAGE(buf, k0)                                                  \
    do {                                                                        \
        _Pragma("unroll")                                                       \
        for (int l = 0; l < 4; l++) {                                           \
            int i = tid + l * 256;                                              \
            int r = i >> 3, c8 = i & 7;                                         \
            cp_async16(&Ah[(buf) * GB_ABUF + r * GB_ALD + c8 * 8],              \
                       &A[(size_t)(bm + r) * K + (k0) + c8 * 8]);               \
        }                                                                       \
        _Pragma("unroll")                                                       \
        for (int l = 0; l < 4; l++) {                                           \
            int i = tid + l * 256;                                              \
            int r = i >> 4, c8 = i & 15;                                        \
            cp_async16(&Bh[(buf) * GB_BBUF + r * GB_BLD + c8 * 8],              \
                       &B[(size_t)((k0) + r) * N + bn + c8 * 8]);               \
        }                                                                       \
        cp_commit();                                                            \
    } while (0)

__global__ __launch_bounds__(256)
void gemm_bf16(const __nv_bfloat16* __restrict__ A, const __nv_bfloat16* __restrict__ B,
               __nv_bfloat16* __restrict__ C, int N, int K)
{
    extern __shared__ __nv_bfloat16 sm_gb[];
    __nv_bfloat16* Ah = sm_gb;                       // 2 * 9216
    __nv_bfloat16* Bh = sm_gb + 2 * GB_ABUF;         // 2 * 8704
    float* wscr = reinterpret_cast<float*>(sm_gb + 2 * GB_ABUF + 2 * GB_BBUF);

    const int tid  = threadIdx.x;
    const int warp = tid >> 5;
    const int lane = tid & 31;
    const int wm   = warp >> 2;          // 0..1 -> rows wm*64
    const int wn   = warp & 3;           // 0..3 -> cols wn*32
    const int bm   = blockIdx.y * 128;
    const int bn   = blockIdx.x * 128;

    GB_LOAD_STAGE(0, 0);

    wmma::fragment<wmma::accumulator, 16, 16, 16, float> acc[4][2];
    #pragma unroll
    for (int mi = 0; mi < 4; mi++)
        #pragma unroll
        for (int ni = 0; ni < 2; ni++)
            wmma::fill_fragment(acc[mi][ni], 0.0f);

    const int KT = K / 64;
    for (int t = 0; t < KT; t++) {
        const int cur = t & 1;
        if (t + 1 < KT) {
            GB_LOAD_STAGE(cur ^ 1, (t + 1) * 64);
            cp_wait_1();
        } else {
            cp_wait_all();
        }
        __syncthreads();

        #pragma unroll
        for (int kk = 0; kk < 64; kk += 16) {
            wmma::fragment<wmma::matrix_a, 16, 16, 16, __nv_bfloat16, wmma::row_major> af[4];
            wmma::fragment<wmma::matrix_b, 16, 16, 16, __nv_bfloat16, wmma::row_major> bf[2];
            #pragma unroll
            for (int mi = 0; mi < 4; mi++)
                wmma::load_matrix_sync(af[mi],
                    &Ah[cur * GB_ABUF + (wm * 64 + mi * 16) * GB_ALD + kk], GB_ALD);
            #pragma unroll
            for (int ni = 0; ni < 2; ni++)
                wmma::load_matrix_sync(bf[ni],
                    &Bh[cur * GB_BBUF + kk * GB_BLD + wn * 32 + ni * 16], GB_BLD);
            #pragma unroll
            for (int mi = 0; mi < 4; mi++)
                #pragma unroll
                for (int ni = 0; ni < 2; ni++)
                    wmma::mma_sync(acc[mi][ni], af[mi], bf[ni], acc[mi][ni]);
        }
        __syncthreads();
    }

    float* wp = &wscr[warp * 272];
    const int srow = lane >> 1;
    const int half = lane & 1;
    #pragma unroll
    for (int mi = 0; mi < 4; mi++)
        #pragma unroll
        for (int ni = 0; ni < 2; ni++) {
            wmma::store_matrix_sync(wp, acc[mi][ni], 16, wmma::mem_row_major);
            __syncwarp();
            const float* sp = &wp[srow * 16 + half * 8];
            uint4 o;
            o.x = pack_bf162(sp[0], sp[1]);
            o.y = pack_bf162(sp[2], sp[3]);
            o.z = pack_bf162(sp[4], sp[5]);
            o.w = pack_bf162(sp[6], sp[7]);
            *reinterpret_cast<uint4*>(
                &C[(size_t)(bm + wm * 64 + mi * 16 + srow) * N
                   + bn + wn * 32 + ni * 16 + half * 8]) = o;
            __syncwarp();
        }
}

// ---------------------------------------------------------------------------
// Wide bf16 GEMM (for V, N=512): block 128x256, 8 warps, warp tile 64x64,
// K-tile 64, cp.async double-buffered. Same issue geometry as gemm_pv.
// smem: A 2*9216*2 + B 2*16896*2 + wscr 8*272*4 = 113152 B.
// ---------------------------------------------------------------------------
#define GW_ALD 72
#define GW_BLD 264
#define GW_ABUF (128 * GW_ALD)     // 9216 bf16
#define GW_BBUF (64 * GW_BLD)      // 16896 bf16
#define GW_SMEM ((2 * GW_ABUF + 2 * GW_BBUF) * 2 + 8 * 272 * 4)

#define GW_LOAD_STAGE(buf, k0)                                                  \
    do {                                                                        \
        _Pragma("unroll")                                                       \
        for (int l = 0; l < 4; l++) {                                           \
            int i = tid + l * 256;                                              \
            int r = i >> 3, c8 = i & 7;                                         \
            cp_async16(&Ah[(buf) * GW_ABUF + r * GW_ALD + c8 * 8],              \
                       &A[(size_t)(bm + r) * K + (k0) + c8 * 8]);               \
        }                                                                       \
        _Pragma("unroll")                                                       \
        for (int l = 0; l < 8; l++) {                                           \
            int i = tid + l * 256;                                              \
            int r = i >> 5, c8 = i & 31;                                        \
            cp_async16(&Bh[(buf) * GW_BBUF + r * GW_BLD + c8 * 8],              \
                       &B[(size_t)((k0) + r) * N + bn + c8 * 8]);               \
        }                                                                       \
        cp_commit();                                                            \
    } while (0)

__global__ __launch_bounds__(256, 1)
void gemm_bf16_wide(const __nv_bfloat16* __restrict__ A, const __nv_bfloat16* __restrict__ B,
                    __nv_bfloat16* __restrict__ C, int N, int K)
{
    extern __shared__ __nv_bfloat16 sm_gw[];
    __nv_bfloat16* Ah = sm_gw;                       // 2 * 9216
    __nv_bfloat16* Bh = sm_gw + 2 * GW_ABUF;         // 2 * 16896
    float* wscr = reinterpret_cast<float*>(sm_gw + 2 * GW_ABUF + 2 * GW_BBUF);

    const int tid  = threadIdx.x;
    const int warp = tid >> 5;
    const int lane = tid & 31;
    const int wm   = warp & 1;           // 0..1 -> rows wm*64
    const int wn   = warp >> 1;          // 0..3 -> cols wn*64
    const int bm   = blockIdx.y * 128;
    const int bn   = blockIdx.x * 256;

    GW_LOAD_STAGE(0, 0);

    wmma::fragment<wmma::accumulator, 16, 16, 16, float> acc[4][4];
    #pragma unroll
    for (int mi = 0; mi < 4; mi++)
        #pragma unroll
        for (int ni = 0; ni < 4; ni++)
            wmma::fill_fragment(acc[mi][ni], 0.0f);

    const int KT = K / 64;
    for (int t = 0; t < KT; t++) {
        const int cur = t & 1;
        if (t + 1 < KT) {
            GW_LOAD_STAGE(cur ^ 1, (t + 1) * 64);
            cp_wait_1();
        } else {
            cp_wait_all();
        }
        __syncthreads();

        #pragma unroll
        for (int kk = 0; kk < 64; kk += 16) {
            wmma::fragment<wmma::matrix_a, 16, 16, 16, __nv_bfloat16, wmma::row_major> af[4];
            wmma::fragment<wmma::matrix_b, 16, 16, 16, __nv_bfloat16, wmma::row_major> bf[4];
            #pragma unroll
            for (int mi = 0; mi < 4; mi++)
                wmma::load_matrix_sync(af[mi],
                    &Ah[cur * GW_ABUF + (wm * 64 + mi * 16) * GW_ALD + kk], GW_ALD);
            #pragma unroll
            for (int ni = 0; ni < 4; ni++)
                wmma::load_matrix_sync(bf[ni],
                    &Bh[cur * GW_BBUF + kk * GW_BLD + wn * 64 + ni * 16], GW_BLD);
            #pragma unroll
            for (int mi = 0; mi < 4; mi++)
                #pragma unroll
                for (int ni = 0; ni < 4; ni++)
                    wmma::mma_sync(acc[mi][ni], af[mi], bf[ni], acc[mi][ni]);
        }
        __syncthreads();
    }

    float* wp = &wscr[warp * 272];
    const int srow = lane >> 1;
    const int half = lane & 1;
    #pragma unroll
    for (int mi = 0; mi < 4; mi++)
        #pragma unroll
        for (int ni = 0; ni < 4; ni++) {
            wmma::store_matrix_sync(wp, acc[mi][ni], 16, wmma::mem_row_major);
            __syncwarp();
            const float* sp = &wp[srow * 16 + half * 8];
            uint4 o;
            o.x = pack_bf162(sp[0], sp[1]);
            o.y = pack_bf162(sp[2], sp[3]);
            o.z = pack_bf162(sp[4], sp[5]);
            o.w = pack_bf162(sp[6], sp[7]);
            *reinterpret_cast<uint4*>(
                &C[(size_t)(bm + wm * 64 + mi * 16 + srow) * N
                   + bn + wn * 64 + ni * 16 + half * 8]) = o;
            __syncwarp();
        }
}

// ---------------------------------------------------------------------------
// exp(S) = exp(f @ g^T), per batch — bf16 MMA. Block tile 128q x 256k,
// 8 warps, warp tile 64x64. Epilogue: per-warp stage -> bf16 store + rowsum
// atomics. smem: Fh 128*72*2 + Gh 256*72*2 + wscr 8*272*4 = 64000 B.
// ---------------------------------------------------------------------------
#define SE_LDH 72
#define SE_SMEM (128 * SE_LDH * 2 + 256 * SE_LDH * 2 + 8 * 272 * 4)

__global__ __launch_bounds__(256)
void gemm_s_exp()
{
    extern __shared__ uint8_t sm_raw[];
    __nv_bfloat16* Fh = reinterpret_cast<__nv_bfloat16*>(sm_raw);               // 128*72
    __nv_bfloat16* Gh = Fh + 128 * SE_LDH;                                      // 256*72
    float* wscr = reinterpret_cast<float*>(sm_raw + (128 + 256) * SE_LDH * 2);  // 8*272

    const int tid  = threadIdx.x;
    const int warp = tid >> 5;
    const int lane = tid & 31;
    const int wm   = warp & 1;         // 0..1 -> q rows wm*64
    const int wn   = warp >> 1;        // 0..3 -> k cols wn*64
    const int bm   = blockIdx.y * 128;
    const int bn   = blockIdx.x * 256;
    const int b    = blockIdx.z;

    const __nv_bfloat16* FG = g_fgh + (size_t)b * NPIX * 128;
    __nv_bfloat16* S = g_sh + (size_t)b * NPIX * NPIX;

    // F tile: 128 rows x 8 chunks of 8 -> 1024 chunks, 4/thread
    #pragma unroll
    for (int l = 0; l < 4; l++) {
        int i = tid + l * 256;
        int r = i >> 3, c8 = i & 7;
        *reinterpret_cast<uint4*>(&Fh[r * SE_LDH + c8 * 8]) =
            *reinterpret_cast<const uint4*>(&FG[(size_t)(bm + r) * 128 + c8 * 8]);
    }
    // G tile: 256 rows x 8 chunks of 8 -> 2048 chunks, 8/thread
    #pragma unroll
    for (int l = 0; l < 8; l++) {
        int i = tid + l * 256;
        int r = i >> 3, c8 = i & 7;
        *reinterpret_cast<uint4*>(&Gh[r * SE_LDH + c8 * 8]) =
            *reinterpret_cast<const uint4*>(&FG[(size_t)(bn + r) * 128 + 64 + c8 * 8]);
    }
    __syncthreads();

    wmma::fragment<wmma::accumulator, 16, 16, 16, float> acc[4][4];
    #pragma unroll
    for (int mi = 0; mi < 4; mi++)
        #pragma unroll
        for (int ni = 0; ni < 4; ni++)
            wmma::fill_fragment(acc[mi][ni], 0.0f);

    #pragma unroll
    for (int kk = 0; kk < DQ; kk += 16) {
        wmma::fragment<wmma::matrix_a, 16, 16, 16, __nv_bfloat16, wmma::row_major> af[4];
        wmma::fragment<wmma::matrix_b, 16, 16, 16, __nv_bfloat16, wmma::col_major> bf[4];
        #pragma unroll
        for (int mi = 0; mi < 4; mi++)
            wmma::load_matrix_sync(af[mi], &Fh[(wm * 64 + mi * 16) * SE_LDH + kk], SE_LDH);
        #pragma unroll
        for (int ni = 0; ni < 4; ni++)
            wmma::load_matrix_sync(bf[ni], &Gh[(wn * 64 + ni * 16) * SE_LDH + kk], SE_LDH);
        #pragma unroll
        for (int mi = 0; mi < 4; mi++)
            #pragma unroll
            for (int ni = 0; ni < 4; ni++)
                wmma::mma_sync(acc[mi][ni], af[mi], bf[ni], acc[mi][ni]);
    }

    // exp on fragments, then per-warp stage -> bf16 store + rowsum atomics
    const float LOG2E = 1.4426950408889634f;
    #pragma unroll
    for (int mi = 0; mi < 4; mi++)
        #pragma unroll
        for (int ni = 0; ni < 4; ni++)
            #pragma unroll
            for (int e = 0; e < acc[mi][ni].num_elements; e++)
                acc[mi][ni].x[e] = exp2f(acc[mi][ni].x[e] * LOG2E);

    float* wp = &wscr[warp * 272];
    const int srow = lane >> 1;
    const int half = lane & 1;
    #pragma unroll
    for (int mi = 0; mi < 4; mi++) {
        float rpart = 0.0f;
        #pragma unroll
        for (int ni = 0; ni < 4; ni++) {
            wmma::store_matrix_sync(wp, acc[mi][ni], 16, wmma::mem_row_major);
            __syncwarp();
            const float* sp = &wp[srow * 16 + half * 8];
            rpart += sp[0] + sp[1] + sp[2] + sp[3] + sp[4] + sp[5] + sp[6] + sp[7];
            uint4 o;
            o.x = pack_bf162(sp[0], sp[1]);
            o.y = pack_bf162(sp[2], sp[3]);
            o.z = pack_bf162(sp[4], sp[5]);
            o.w = pack_bf162(sp[6], sp[7]);
            *reinterpret_cast<uint4*>(
                &S[(size_t)(bm + wm * 64 + mi * 16 + srow) * NPIX
                   + bn + wn * 64 + ni * 16 + half * 8]) = o;
            __syncwarp();
        }
        rpart += __shfl_xor_sync(0xFFFFFFFFu, rpart, 1);
        if (half == 0)
            atomicAdd(&g_rsum[b * NPIX + bm + wm * 64 + mi * 16 + srow], rpart);
    }
}

// ---------------------------------------------------------------------------
// out = gamma * (P @ V) + x. M-tile 128, N-tile 256, K-tile 64.
// 256 threads, 8 warps, warp tile 64x64. 3-stage cp.async pipeline.
// ---------------------------------------------------------------------------
#define PV_ALD 72
#define PV_BLD 264
#define PV_ABUF (128 * PV_ALD)      // 9216 bf16
#define PV_BBUF (64 * PV_BLD)       // 16896 bf16
#define PV_TILES (NPIX / 64)        // 64
#define PV_SMEM ((3 * PV_ABUF + 3 * PV_BBUF) * 2 + 8 * 272 * 4)    // 165376

#define PV_LOAD_STAGE(buf, k0)                                                  \
    do {                                                                        \
        _Pragma("unroll")                                                       \
        for (int l = 0; l < 4; l++) {                                           \
            int i = tid + l * 256;                                              \
            int r = i >> 3, c8 = i & 7;                                         \
            cp_async16(&As[(buf) * PV_ABUF + r * PV_ALD + c8 * 8],              \
                       &S[(size_t)(bm + r) * NPIX + (k0) + c8 * 8]);            \
        }                                                                       \
        _Pragma("unroll")                                                       \
        for (int l = 0; l < 8; l++) {                                           \
            int i = tid + l * 256;                                              \
            int r = i >> 5, c8 = i & 31;                                        \
            cp_async16(&Bs[(buf) * PV_BBUF + r * PV_BLD + c8 * 8],              \
                       &V[(size_t)((k0) + r) * CH + cn0 + c8 * 8]);             \
        }                                                                       \
        cp_commit();                                                            \
    } while (0)

__global__ __launch_bounds__(256, 1)
void gemm_pv(const float* __restrict__ x, const float* __restrict__ gam_p,
             float* __restrict__ out)
{
    extern __shared__ __nv_bfloat16 sm_pv[];
    __nv_bfloat16* As = sm_pv;                        // 3 * 9216
    __nv_bfloat16* Bs = sm_pv + 3 * PV_ABUF;          // 3 * 16896
    float* wscr = reinterpret_cast<float*>(sm_pv + 3 * PV_ABUF + 3 * PV_BBUF);

    const int tid  = threadIdx.x;
    const int warp = tid >> 5;
    const int lane = tid & 31;
    const int wm   = warp & 1;             // 0..1 -> row offset wm*64
    const int wn   = warp >> 1;            // 0..3 -> col offset wn*64
    const int bm   = blockIdx.x * 128;
    const int nh   = blockIdx.y;           // 0..1 -> channel half
    const int b    = blockIdx.z;
    const int cn0  = nh * 256;

    const __nv_bfloat16* S = g_sh + (size_t)b * NPIX * NPIX;
    const __nv_bfloat16* V = g_vh + (size_t)b * NPIX * CH;

    PV_LOAD_STAGE(0, 0);
    PV_LOAD_STAGE(1, 64);
    cp_wait_1();
    __syncthreads();

    wmma::fragment<wmma::accumulator, 16, 16, 16, float> acc[4][4];
    #pragma unroll
    for (int mi = 0; mi < 4; mi++)
        #pragma unroll
        for (int ni = 0; ni < 4; ni++)
            wmma::fill_fragment(acc[mi][ni], 0.0f);

    for (int t = 0; t < PV_TILES; t++) {
        const int cur = t % 3;
        if (t + 2 < PV_TILES)
            PV_LOAD_STAGE((t + 2) % 3, (t + 2) * 64);

        #pragma unroll
        for (int kk = 0; kk < 64; kk += 16) {
            wmma::fragment<wmma::matrix_a, 16, 16, 16, __nv_bfloat16, wmma::row_major> af[4];
            wmma::fragment<wmma::matrix_b, 16, 16, 16, __nv_bfloat16, wmma::row_major> bf[4];
            #pragma unroll
            for (int mi = 0; mi < 4; mi++)
                wmma::load_matrix_sync(af[mi],
                    &As[cur * PV_ABUF + (wm * 64 + mi * 16) * PV_ALD + kk], PV_ALD);
            #pragma unroll
            for (int ni = 0; ni < 4; ni++)
                wmma::load_matrix_sync(bf[ni],
                    &Bs[cur * PV_BBUF + kk * PV_BLD + wn * 64 + ni * 16], PV_BLD);
            #pragma unroll
            for (int mi = 0; mi < 4; mi++)
                #pragma unroll
                for (int ni = 0; ni < 4; ni++)
                    wmma::mma_sync(acc[mi][ni], af[mi], bf[ni], acc[mi][ni]);
        }

        if (t + 1 < PV_TILES) {
            if (t + 2 < PV_TILES) cp_wait_1();
            else                  cp_wait_all();
            __syncthreads();
        }
    }

    // ---- epilogue: per-warp fragment stage -> normalize -> gamma -> +x ----
    __syncthreads();
    const float gam = gam_p[0];
    float* wp = &wscr[warp * 272];
    const int srow = lane >> 1;
    const int half = lane & 1;

    #pragma unroll
    for (int mi = 0; mi < 4; mi++)
        #pragma unroll
        for (int ni = 0; ni < 4; ni++) {
            wmma::store_matrix_sync(wp, acc[mi][ni], 16, wmma::mem_row_major);
            __syncwarp();
            const int r = wm * 64 + mi * 16 + srow;
            const float sc = gam / g_rsum[b * NPIX + bm + r];
            const float* sp = &wp[srow * 16 + half * 8];
            size_t gidx = ((size_t)b * NPIX + bm + r) * CH
                          + cn0 + wn * 64 + ni * 16 + half * 8;
            float4 x1 = *reinterpret_cast<const float4*>(&x[gidx]);
            float4 x2 = *reinterpret_cast<const float4*>(&x[gidx + 4]);
            float4 o1, o2;
            o1.x = sp[0] * sc + x1.x;  o1.y = sp[1] * sc + x1.y;
            o1.z = sp[2] * sc + x1.z;  o1.w = sp[3] * sc + x1.w;
            o2.x = sp[4] * sc + x2.x;  o2.y = sp[5] * sc + x2.y;
            o2.z = sp[6] * sc + x2.z;  o2.w = sp[7] * sc + x2.w;
            *reinterpret_cast<float4*>(&out[gidx])     = o1;
            *reinterpret_cast<float4*>(&out[gidx + 4]) = o2;
            __syncwarp();
        }
}

// ---------------------------------------------------------------------------
extern "C" void kernel_launch(void* const* d_in, const int* in_sizes, int n_in,
                              void* d_out, int out_size)
{
    const float* x     = (const float*)d_in[0];
    const float* wf    = (const float*)d_in[1];
    const float* wg    = (const float*)d_in[2];
    const float* wh    = (const float*)d_in[3];
    const float* gamma = (const float*)d_in[4];
    float* out = (float*)d_out;

    __nv_bfloat16 *pxh, *pwhh, *pwfg, *pfgh, *pvh;
    cudaGetSymbolAddress((void**)&pxh,  g_xh);
    cudaGetSymbolAddress((void**)&pwhh, g_whh);
    cudaGetSymbolAddress((void**)&pwfg, g_wfg);
    cudaGetSymbolAddress((void**)&pfgh, g_fgh);
    cudaGetSymbolAddress((void**)&pvh,  g_vh);

    static cudaStream_t s2 = nullptr;
    static cudaEvent_t evX = nullptr, evV = nullptr;
    static bool attr_done = false;
    if (!attr_done) {
        cudaFuncSetAttribute(gemm_bf16,      cudaFuncAttributeMaxDynamicSharedMemorySize, GB_SMEM);
        cudaFuncSetAttribute(gemm_bf16_wide, cudaFuncAttributeMaxDynamicSharedMemorySize, GW_SMEM);
        cudaFuncSetAttribute(gemm_s_exp,     cudaFuncAttributeMaxDynamicSharedMemorySize, SE_SMEM);
        cudaFuncSetAttribute(gemm_pv,        cudaFuncAttributeMaxDynamicSharedMemorySize, PV_SMEM);
        cudaStreamCreateWithFlags(&s2, cudaStreamNonBlocking);
        cudaEventCreateWithFlags(&evX, cudaEventDisableTiming);
        cudaEventCreateWithFlags(&evV, cudaEventDisableTiming);
        attr_done = true;
    }

    // ---- main stream: x conversion, then fork ----
    cvt_f32_bf16<<<(MTOT * CH) / 4 / 256, 256>>>(x, pxh);
    cudaEventRecord(evX, 0);

    // ---- side stream: Wh conversion + V GEMM ----
    cudaStreamWaitEvent(s2, evX, 0);
    cvt_f32_bf16<<<(CH * CH) / 4 / 256, 256, 0, s2>>>(wh, pwhh);
    gemm_bf16_wide<<<dim3(CH / 256, MTOT / 128), 256, GW_SMEM, s2>>>(pxh, pwhh, pvh, CH, CH);
    cudaEventRecord(evV, s2);

    // ---- main stream: fg chain ----
    build_wfg<<<(CH * DQ) / 256, 256>>>(wf, wg);
    zero_rsum<<<MTOT / 1024, 1024>>>();

    // [f|g] = x @ [Wf|Wg]
    gemm_bf16<<<dim3(1, MTOT / 128), 256, GB_SMEM>>>(pxh, pwfg, pfgh, 2 * DQ, CH);

    // exp(S) = exp(f @ g^T) with rowsum atomics
    gemm_s_exp<<<dim3(NPIX / 256, NPIX / 128, BATCH), 256, SE_SMEM>>>();

    // ---- join: PV needs both S and V ----
    cudaStreamWaitEvent(0, evV, 0);
    gemm_pv<<<dim3(NPIX / 128, 2, BATCH), 256, PV_SMEM>>>(x, gamma, out);
}

// round 16
// speedup vs baseline: 1.0359x; 1.0359x over previous
#include <cuda_runtime.h>
#include <cuda_bf16.h>
#include <mma.h>
#include <math.h>
#include <stdint.h>

using namespace nvcuda;

#define BATCH 4
#define NPIX  4096
#define CH    512
#define DQ    64
#define MTOT  (BATCH*NPIX)

// Scratch (device globals: the sanctioned no-alloc workaround)
static __device__ __nv_bfloat16  g_xh[(size_t)MTOT * CH];           // bf16 x (16 MB)
static __device__ __nv_bfloat16  g_whh[CH * CH];                    // bf16 Wh
static __device__ __nv_bfloat16  g_wfg[CH * 2 * DQ];                // bf16 [Wf|Wg] 512x128
static __device__ __nv_bfloat16  g_fgh[MTOT * 2 * DQ];              // bf16 [f|g] (4 MB)
static __device__ __nv_bfloat16  g_vh[(size_t)MTOT * CH];           // 16 MB
static __device__ __nv_bfloat16  g_sh[(size_t)BATCH * NPIX * NPIX]; // 128 MB exp(S)
static __device__ float          g_rsum[MTOT];                      // row sums

// ---------------------------------------------------------------------------
// cp.async helpers
// ---------------------------------------------------------------------------
__device__ __forceinline__ void cp_async16(void* smem_dst, const void* gmem_src) {
    uint32_t sa = (uint32_t)__cvta_generic_to_shared(smem_dst);
    asm volatile("cp.async.cg.shared.global [%0], [%1], 16;\n" :: "r"(sa), "l"(gmem_src));
}
__device__ __forceinline__ void cp_commit() {
    asm volatile("cp.async.commit_group;\n");
}
__device__ __forceinline__ void cp_wait_all() {
    asm volatile("cp.async.wait_group 0;\n");
}
__device__ __forceinline__ void cp_wait_1() {
    asm volatile("cp.async.wait_group 1;\n");
}

__device__ __forceinline__ uint32_t pack_bf162(float lo, float hi) {
    __nv_bfloat162 h = __floats2bfloat162_rn(lo, hi);
    return *reinterpret_cast<uint32_t*>(&h);
}

// ---------------------------------------------------------------------------
// small prep kernels
// ---------------------------------------------------------------------------
__global__ void zero_rsum()
{
    g_rsum[blockIdx.x * 1024 + threadIdx.x] = 0.0f;
}

// float -> bf16, 4 elems per thread
__global__ void cvt_f32_bf16(const float* __restrict__ src, __nv_bfloat16* __restrict__ dst)
{
    const size_t i = (size_t)blockIdx.x * 256 + threadIdx.x;
    float4 v = reinterpret_cast<const float4*>(src)[i];
    uint2 o;
    o.x = pack_bf162(v.x, v.y);
    o.y = pack_bf162(v.z, v.w);
    reinterpret_cast<uint2*>(dst)[i] = o;
}

// build Wfg[512][128] = [Wf | Wg] in bf16
__global__ void build_wfg(const float* __restrict__ wf, const float* __restrict__ wg)
{
    const int i = blockIdx.x * 256 + threadIdx.x;   // 0 .. 512*64-1
    const int r = i >> 6, c = i & 63;
    g_wfg[r * 128 + c]      = __float2bfloat16(wf[r * 64 + c]);
    g_wfg[r * 128 + 64 + c] = __float2bfloat16(wg[r * 64 + c]);
}

// ---------------------------------------------------------------------------
// Narrow bf16 GEMM: block 128x128, 8 warps, warp tile 64x32, K-tile 64,
// cp.async double-buffered. (fg projection and V GEMM)
// ---------------------------------------------------------------------------
#define GB_ALD 72
#define GB_BLD 136
#define GB_ABUF (128 * GB_ALD)     // 9216 bf16
#define GB_BBUF (64 * GB_BLD)      // 8704 bf16
#define GB_SMEM ((2 * GB_ABUF + 2 * GB_BBUF) * 2 + 8 * 272 * 4)

#define GB_LOAD_STAGE(buf, k0)                                                  \
    do {                                                                        \
        _Pragma("unroll")                                                       \
        for (int l = 0; l < 4; l++) {                                           \
            int i = tid + l * 256;                                              \
            int r = i >> 3, c8 = i & 7;                                         \
            cp_async16(&Ah[(buf) * GB_ABUF + r * GB_ALD + c8 * 8],              \
                       &A[(size_t)(bm + r) * K + (k0) + c8 * 8]);               \
        }                                                                       \
        _Pragma("unroll")                                                       \
        for (int l = 0; l < 4; l++) {                                           \
            int i = tid + l * 256;                                              \
            int r = i >> 4, c8 = i & 15;                                        \
            cp_async16(&Bh[(buf) * GB_BBUF + r * GB_BLD + c8 * 8],              \
                       &B[(size_t)((k0) + r) * N + bn + c8 * 8]);               \
        }                                                                       \
        cp_commit();                                                            \
    } while (0)

__global__ __launch_bounds__(256)
void gemm_bf16(const __nv_bfloat16* __restrict__ A, const __nv_bfloat16* __restrict__ B,
               __nv_bfloat16* __restrict__ C, int N, int K)
{
    extern __shared__ __nv_bfloat16 sm_gb[];
    __nv_bfloat16* Ah = sm_gb;                       // 2 * 9216
    __nv_bfloat16* Bh = sm_gb + 2 * GB_ABUF;         // 2 * 8704
    float* wscr = reinterpret_cast<float*>(sm_gb + 2 * GB_ABUF + 2 * GB_BBUF);

    const int tid  = threadIdx.x;
    const int warp = tid >> 5;
    const int lane = tid & 31;
    const int wm   = warp >> 2;          // 0..1 -> rows wm*64
    const int wn   = warp & 3;           // 0..3 -> cols wn*32
    const int bm   = blockIdx.y * 128;
    const int bn   = blockIdx.x * 128;

    GB_LOAD_STAGE(0, 0);

    wmma::fragment<wmma::accumulator, 16, 16, 16, float> acc[4][2];
    #pragma unroll
    for (int mi = 0; mi < 4; mi++)
        #pragma unroll
        for (int ni = 0; ni < 2; ni++)
            wmma::fill_fragment(acc[mi][ni], 0.0f);

    const int KT = K / 64;
    for (int t = 0; t < KT; t++) {
        const int cur = t & 1;
        if (t + 1 < KT) {
            GB_LOAD_STAGE(cur ^ 1, (t + 1) * 64);
            cp_wait_1();
        } else {
            cp_wait_all();
        }
        __syncthreads();

        #pragma unroll
        for (int kk = 0; kk < 64; kk += 16) {
            wmma::fragment<wmma::matrix_a, 16, 16, 16, __nv_bfloat16, wmma::row_major> af[4];
            wmma::fragment<wmma::matrix_b, 16, 16, 16, __nv_bfloat16, wmma::row_major> bf[2];
            #pragma unroll
            for (int mi = 0; mi < 4; mi++)
                wmma::load_matrix_sync(af[mi],
                    &Ah[cur * GB_ABUF + (wm * 64 + mi * 16) * GB_ALD + kk], GB_ALD);
            #pragma unroll
            for (int ni = 0; ni < 2; ni++)
                wmma::load_matrix_sync(bf[ni],
                    &Bh[cur * GB_BBUF + kk * GB_BLD + wn * 32 + ni * 16], GB_BLD);
            #pragma unroll
            for (int mi = 0; mi < 4; mi++)
                #pragma unroll
                for (int ni = 0; ni < 2; ni++)
                    wmma::mma_sync(acc[mi][ni], af[mi], bf[ni], acc[mi][ni]);
        }
        __syncthreads();
    }

    float* wp = &wscr[warp * 272];
    const int srow = lane >> 1;
    const int half = lane & 1;
    #pragma unroll
    for (int mi = 0; mi < 4; mi++)
        #pragma unroll
        for (int ni = 0; ni < 2; ni++) {
            wmma::store_matrix_sync(wp, acc[mi][ni], 16, wmma::mem_row_major);
            __syncwarp();
            const float* sp = &wp[srow * 16 + half * 8];
            uint4 o;
            o.x = pack_bf162(sp[0], sp[1]);
            o.y = pack_bf162(sp[2], sp[3]);
            o.z = pack_bf162(sp[4], sp[5]);
            o.w = pack_bf162(sp[6], sp[7]);
            *reinterpret_cast<uint4*>(
                &C[(size_t)(bm + wm * 64 + mi * 16 + srow) * N
                   + bn + wn * 32 + ni * 16 + half * 8]) = o;
            __syncwarp();
        }
}

// ---------------------------------------------------------------------------
// exp(S) = exp(f @ g^T), per batch — bf16 MMA (m16n16k16).
// 128x128 tile, K=64 in 4 steps. Epilogue: per-warp stage -> bf16 store +
// f32 row-sum partials atomically accumulated into g_rsum.
// __launch_bounds__(256, 2): cap regs at 128 -> 2 blocks/SM (short mainloop,
// latency-exposed at 1 block/SM per the R10 profile: regs=194, occ=12%).
// ---------------------------------------------------------------------------
#define SE_LDH 72
#define SE_SMEM (2 * 128 * SE_LDH * 2 + 8 * 272 * 4)

__global__ __launch_bounds__(256, 2)
void gemm_s_exp()
{
    extern __shared__ uint8_t sm_raw[];
    __nv_bfloat16* Fh = reinterpret_cast<__nv_bfloat16*>(sm_raw);               // 128*72
    __nv_bfloat16* Gh = Fh + 128 * SE_LDH;                                      // 128*72
    float* wscr = reinterpret_cast<float*>(sm_raw + 2 * 128 * SE_LDH * 2);      // 8*272

    const int tid  = threadIdx.x;
    const int warp = tid >> 5;
    const int lane = tid & 31;
    const int wm   = warp >> 2;        // 0..1 -> rows wm*64
    const int wn   = warp & 3;         // 0..3 -> cols wn*32
    const int bm   = blockIdx.y * 128;
    const int bn   = blockIdx.x * 128;
    const int b    = blockIdx.z;

    const __nv_bfloat16* FG = g_fgh + (size_t)b * NPIX * 128;
    __nv_bfloat16* S = g_sh + (size_t)b * NPIX * NPIX;

    #pragma unroll
    for (int l = 0; l < 4; l++) {
        int i = tid + l * 256;
        int r = i >> 3, c8 = i & 7;
        *reinterpret_cast<uint4*>(&Fh[r * SE_LDH + c8 * 8]) =
            *reinterpret_cast<const uint4*>(&FG[(size_t)(bm + r) * 128 + c8 * 8]);
        *reinterpret_cast<uint4*>(&Gh[r * SE_LDH + c8 * 8]) =
            *reinterpret_cast<const uint4*>(&FG[(size_t)(bn + r) * 128 + 64 + c8 * 8]);
    }
    __syncthreads();

    wmma::fragment<wmma::accumulator, 16, 16, 16, float> acc[4][2];
    #pragma unroll
    for (int mi = 0; mi < 4; mi++)
        #pragma unroll
        for (int ni = 0; ni < 2; ni++)
            wmma::fill_fragment(acc[mi][ni], 0.0f);

    #pragma unroll
    for (int kk = 0; kk < DQ; kk += 16) {
        wmma::fragment<wmma::matrix_a, 16, 16, 16, __nv_bfloat16, wmma::row_major> af[4];
        wmma::fragment<wmma::matrix_b, 16, 16, 16, __nv_bfloat16, wmma::col_major> bf[2];
        #pragma unroll
        for (int mi = 0; mi < 4; mi++)
            wmma::load_matrix_sync(af[mi], &Fh[(wm * 64 + mi * 16) * SE_LDH + kk], SE_LDH);
        #pragma unroll
        for (int ni = 0; ni < 2; ni++)
            wmma::load_matrix_sync(bf[ni], &Gh[(wn * 32 + ni * 16) * SE_LDH + kk], SE_LDH);
        #pragma unroll
        for (int mi = 0; mi < 4; mi++)
            #pragma unroll
            for (int ni = 0; ni < 2; ni++)
                wmma::mma_sync(acc[mi][ni], af[mi], bf[ni], acc[mi][ni]);
    }

    // exp on fragments, then per-warp stage -> bf16 store + rowsum atomics
    const float LOG2E = 1.4426950408889634f;
    #pragma unroll
    for (int mi = 0; mi < 4; mi++)
        #pragma unroll
        for (int ni = 0; ni < 2; ni++)
            #pragma unroll
            for (int e = 0; e < acc[mi][ni].num_elements; e++)
                acc[mi][ni].x[e] = exp2f(acc[mi][ni].x[e] * LOG2E);

    float* wp = &wscr[warp * 272];
    const int srow = lane >> 1;
    const int half = lane & 1;
    #pragma unroll
    for (int mi = 0; mi < 4; mi++) {
        float rpart = 0.0f;
        #pragma unroll
        for (int ni = 0; ni < 2; ni++) {
            wmma::store_matrix_sync(wp, acc[mi][ni], 16, wmma::mem_row_major);
            __syncwarp();
            const float* sp = &wp[srow * 16 + half * 8];
            rpart += sp[0] + sp[1] + sp[2] + sp[3] + sp[4] + sp[5] + sp[6] + sp[7];
            uint4 o;
            o.x = pack_bf162(sp[0], sp[1]);
            o.y = pack_bf162(sp[2], sp[3]);
            o.z = pack_bf162(sp[4], sp[5]);
            o.w = pack_bf162(sp[6], sp[7]);
            *reinterpret_cast<uint4*>(
                &S[(size_t)(bm + wm * 64 + mi * 16 + srow) * NPIX
                   + bn + wn * 32 + ni * 16 + half * 8]) = o;
            __syncwarp();
        }
        rpart += __shfl_xor_sync(0xFFFFFFFFu, rpart, 1);
        if (half == 0)
            atomicAdd(&g_rsum[b * NPIX + bm + wm * 64 + mi * 16 + srow], rpart);
    }
}

// ---------------------------------------------------------------------------
// out = gamma * (P @ V) + x. M-tile 128, N-tile 256, K-tile 64.
// 256 threads, 8 warps, warp tile 64x64. 3-stage cp.async pipeline.
// ---------------------------------------------------------------------------
#define PV_ALD 72
#define PV_BLD 264
#define PV_ABUF (128 * PV_ALD)      // 9216 bf16
#define PV_BBUF (64 * PV_BLD)       // 16896 bf16
#define PV_TILES (NPIX / 64)        // 64
#define PV_SMEM ((3 * PV_ABUF + 3 * PV_BBUF) * 2 + 8 * 272 * 4)    // 165376

#define PV_LOAD_STAGE(buf, k0)                                                  \
    do {                                                                        \
        _Pragma("unroll")                                                       \
        for (int l = 0; l < 4; l++) {                                           \
            int i = tid + l * 256;                                              \
            int r = i >> 3, c8 = i & 7;                                         \
            cp_async16(&As[(buf) * PV_ABUF + r * PV_ALD + c8 * 8],              \
                       &S[(size_t)(bm + r) * NPIX + (k0) + c8 * 8]);            \
        }                                                                       \
        _Pragma("unroll")                                                       \
        for (int l = 0; l < 8; l++) {                                           \
            int i = tid + l * 256;                                              \
            int r = i >> 5, c8 = i & 31;                                        \
            cp_async16(&Bs[(buf) * PV_BBUF + r * PV_BLD + c8 * 8],              \
                       &V[(size_t)((k0) + r) * CH + cn0 + c8 * 8]);             \
        }                                                                       \
        cp_commit();                                                            \
    } while (0)

__global__ __launch_bounds__(256, 1)
void gemm_pv(const float* __restrict__ x, const float* __restrict__ gam_p,
             float* __restrict__ out)
{
    extern __shared__ __nv_bfloat16 sm_pv[];
    __nv_bfloat16* As = sm_pv;                        // 3 * 9216
    __nv_bfloat16* Bs = sm_pv + 3 * PV_ABUF;          // 3 * 16896
    float* wscr = reinterpret_cast<float*>(sm_pv + 3 * PV_ABUF + 3 * PV_BBUF);

    const int tid  = threadIdx.x;
    const int warp = tid >> 5;
    const int lane = tid & 31;
    const int wm   = warp & 1;             // 0..1 -> row offset wm*64
    const int wn   = warp >> 1;            // 0..3 -> col offset wn*64
    const int bm   = blockIdx.x * 128;
    const int nh   = blockIdx.y;           // 0..1 -> channel half
    const int b    = blockIdx.z;
    const int cn0  = nh * 256;

    const __nv_bfloat16* S = g_sh + (size_t)b * NPIX * NPIX;
    const __nv_bfloat16* V = g_vh + (size_t)b * NPIX * CH;

    PV_LOAD_STAGE(0, 0);
    PV_LOAD_STAGE(1, 64);
    cp_wait_1();
    __syncthreads();

    wmma::fragment<wmma::accumulator, 16, 16, 16, float> acc[4][4];
    #pragma unroll
    for (int mi = 0; mi < 4; mi++)
        #pragma unroll
        for (int ni = 0; ni < 4; ni++)
            wmma::fill_fragment(acc[mi][ni], 0.0f);

    for (int t = 0; t < PV_TILES; t++) {
        const int cur = t % 3;
        if (t + 2 < PV_TILES)
            PV_LOAD_STAGE((t + 2) % 3, (t + 2) * 64);

        #pragma unroll
        for (int kk = 0; kk < 64; kk += 16) {
            wmma::fragment<wmma::matrix_a, 16, 16, 16, __nv_bfloat16, wmma::row_major> af[4];
            wmma::fragment<wmma::matrix_b, 16, 16, 16, __nv_bfloat16, wmma::row_major> bf[4];
            #pragma unroll
            for (int mi = 0; mi < 4; mi++)
                wmma::load_matrix_sync(af[mi],
                    &As[cur * PV_ABUF + (wm * 64 + mi * 16) * PV_ALD + kk], PV_ALD);
            #pragma unroll
            for (int ni = 0; ni < 4; ni++)
                wmma::load_matrix_sync(bf[ni],
                    &Bs[cur * PV_BBUF + kk * PV_BLD + wn * 64 + ni * 16], PV_BLD);
            #pragma unroll
            for (int mi = 0; mi < 4; mi++)
                #pragma unroll
                for (int ni = 0; ni < 4; ni++)
                    wmma::mma_sync(acc[mi][ni], af[mi], bf[ni], acc[mi][ni]);
        }

        if (t + 1 < PV_TILES) {
            if (t + 2 < PV_TILES) cp_wait_1();
            else                  cp_wait_all();
            __syncthreads();
        }
    }

    // ---- epilogue: per-warp fragment stage -> normalize -> gamma -> +x ----
    __syncthreads();
    const float gam = gam_p[0];
    float* wp = &wscr[warp * 272];
    const int srow = lane >> 1;
    const int half = lane & 1;

    #pragma unroll
    for (int mi = 0; mi < 4; mi++)
        #pragma unroll
        for (int ni = 0; ni < 4; ni++) {
            wmma::store_matrix_sync(wp, acc[mi][ni], 16, wmma::mem_row_major);
            __syncwarp();
            const int r = wm * 64 + mi * 16 + srow;
            const float sc = gam / g_rsum[b * NPIX + bm + r];
            const float* sp = &wp[srow * 16 + half * 8];
            size_t gidx = ((size_t)b * NPIX + bm + r) * CH
                          + cn0 + wn * 64 + ni * 16 + half * 8;
            float4 x1 = *reinterpret_cast<const float4*>(&x[gidx]);
            float4 x2 = *reinterpret_cast<const float4*>(&x[gidx + 4]);
            float4 o1, o2;
            o1.x = sp[0] * sc + x1.x;  o1.y = sp[1] * sc + x1.y;
            o1.z = sp[2] * sc + x1.z;  o1.w = sp[3] * sc + x1.w;
            o2.x = sp[4] * sc + x2.x;  o2.y = sp[5] * sc + x2.y;
            o2.z = sp[6] * sc + x2.z;  o2.w = sp[7] * sc + x2.w;
            *reinterpret_cast<float4*>(&out[gidx])     = o1;
            *reinterpret_cast<float4*>(&out[gidx + 4]) = o2;
            __syncwarp();
        }
}

// ---------------------------------------------------------------------------
extern "C" void kernel_launch(void* const* d_in, const int* in_sizes, int n_in,
                              void* d_out, int out_size)
{
    const float* x     = (const float*)d_in[0];
    const float* wf    = (const float*)d_in[1];
    const float* wg    = (const float*)d_in[2];
    const float* wh    = (const float*)d_in[3];
    const float* gamma = (const float*)d_in[4];
    float* out = (float*)d_out;

    __nv_bfloat16 *pxh, *pwhh, *pwfg, *pfgh, *pvh;
    cudaGetSymbolAddress((void**)&pxh,  g_xh);
    cudaGetSymbolAddress((void**)&pwhh, g_whh);
    cudaGetSymbolAddress((void**)&pwfg, g_wfg);
    cudaGetSymbolAddress((void**)&pfgh, g_fgh);
    cudaGetSymbolAddress((void**)&pvh,  g_vh);

    static cudaStream_t s2 = nullptr;
    static cudaEvent_t evX = nullptr, evV = nullptr;
    static bool attr_done = false;
    if (!attr_done) {
        cudaFuncSetAttribute(gemm_bf16,  cudaFuncAttributeMaxDynamicSharedMemorySize, GB_SMEM);
        cudaFuncSetAttribute(gemm_s_exp, cudaFuncAttributeMaxDynamicSharedMemorySize, SE_SMEM);
        cudaFuncSetAttribute(gemm_pv,    cudaFuncAttributeMaxDynamicSharedMemorySize, PV_SMEM);
        cudaStreamCreateWithFlags(&s2, cudaStreamNonBlocking);
        cudaEventCreateWithFlags(&evX, cudaEventDisableTiming);
        cudaEventCreateWithFlags(&evV, cudaEventDisableTiming);
        attr_done = true;
    }

    // ---- main stream: x conversion, then fork ----
    cvt_f32_bf16<<<(MTOT * CH) / 4 / 256, 256>>>(x, pxh);
    cudaEventRecord(evX, 0);

    // ---- side stream: Wh conversion + V GEMM ----
    cudaStreamWaitEvent(s2, evX, 0);
    cvt_f32_bf16<<<(CH * CH) / 4 / 256, 256, 0, s2>>>(wh, pwhh);
    gemm_bf16<<<dim3(CH / 128, MTOT / 128), 256, GB_SMEM, s2>>>(pxh, pwhh, pvh, CH, CH);
    cudaEventRecord(evV, s2);

    // ---- main stream: fg chain ----
    build_wfg<<<(CH * DQ) / 256, 256>>>(wf, wg);
    zero_rsum<<<MTOT / 1024, 1024>>>();

    // [f|g] = x @ [Wf|Wg]
    gemm_bf16<<<dim3(1, MTOT / 128), 256, GB_SMEM>>>(pxh, pwfg, pfgh, 2 * DQ, CH);

    // exp(S) = exp(f @ g^T) with rowsum atomics
    gemm_s_exp<<<dim3(NPIX / 128, NPIX / 128, BATCH), 256, SE_SMEM>>>();

    // ---- join: PV needs both S and V ----
    cudaStreamWaitEvent(0, evV, 0);
    gemm_pv<<<dim3(NPIX / 128, 2, BATCH), 256, PV_SMEM>>>(x, gamma, out);
}